// round 2
// baseline (speedup 1.0000x reference)
#include <cuda_runtime.h>
#include <math.h>

#define T 1024
#define B 32
#define INPUT_DIM 256
#define H 512
#define H3 1536
#define FEAT (2*H)

#define NCTAS_REC 128
#define CTAS_PER_DIR 64
#define HID_PER_CTA 8           // 512 / 64

// ---- device scratch (static __device__: no allocation) ----
__device__ __align__(256) float g_xT[T * INPUT_DIM * B];              // 33.5 MB
__device__ __align__(256) float g_Xi[2u * T * H3 * B];                // 402 MB
__device__ __align__(256) float g_yA[T * FEAT * B];                   // 134 MB
__device__ __align__(256) float g_yB[T * FEAT * B];                   // 134 MB
__device__ __align__(256) float g_h[2][2 * H * B];                    // double-buffered state
__device__ unsigned long long g_cnt;                                  // grid barrier (monotonic)
__device__ unsigned long long g_rel;

// ---------------- grid barrier (ticket based, replay-safe: monotonic) --------
__device__ __forceinline__ void grid_sync() {
    __syncthreads();
    if (threadIdx.x == 0) {
        __threadfence();
        unsigned long long a = atomicAdd(&g_cnt, 1ull) + 1ull;
        unsigned long long goal = ((a + NCTAS_REC - 1) / NCTAS_REC) * NCTAS_REC;
        if (a == goal) {
            atomicMax(&g_rel, goal);
        } else {
            while (*((volatile unsigned long long*)&g_rel) < goal) { }
        }
        __threadfence();
    }
    __syncthreads();
}

// ---------------- transpose x[t][b][k] -> g_xT[t][k][b] ----------------------
__global__ void transpose_x(const float* __restrict__ x) {
    __shared__ float sm[B][INPUT_DIM + 1];   // pad -> conflict free
    int t = blockIdx.x;
    const float* xin = x + (size_t)t * B * INPUT_DIM;
    for (int i = threadIdx.x; i < B * INPUT_DIM; i += 256) {
        int b = i >> 8, k = i & 255;
        sm[b][k] = xin[i];
    }
    __syncthreads();
    float* xo = g_xT + (size_t)t * INPUT_DIM * B;
    for (int i = threadIdx.x; i < B * INPUT_DIM; i += 256) {
        int k = i >> 5, b = i & 31;
        xo[i] = sm[b][k];
    }
}

// ---------------- Xi GEMM: Xi[dir][t][g][b] = A[t][:][b] . W[dir][g][:] + bih
// A layout: [t][K][b].  Grid: (T, 12): 12 = 2 dirs * 6 g-blocks of 256.
__global__ __launch_bounds__(256) void gemm_xi(const float* __restrict__ A,
                                               const float* __restrict__ Wih,
                                               const float* __restrict__ bih,
                                               int K) {
    __shared__ float Ws[32 * 264];   // [kk][g 0..255], padded stride
    __shared__ float Xs[32 * 32];    // [kk][b]
    int t   = blockIdx.x;
    int by  = blockIdx.y;
    int dir = by / 6;
    int g0  = (by % 6) * 256;

    const float* Wp = Wih + ((size_t)dir * H3 + g0) * (size_t)K;
    const float* Ap = A + (size_t)t * K * B;

    int gT = threadIdx.x & 31;       // 32 g-groups of 8
    int bT = threadIdx.x >> 5;       // 8 b-groups of 4
    int kk0 = threadIdx.x & 31;
    int gb  = threadIdx.x >> 5;

    float acc[8][4];
#pragma unroll
    for (int i = 0; i < 8; i++)
#pragma unroll
        for (int j = 0; j < 4; j++) acc[i][j] = 0.f;

    for (int k0 = 0; k0 < K; k0 += 32) {
        // stage W tile: Ws[kk][g]
#pragma unroll
        for (int gi = 0; gi < 32; gi++) {
            int g = gb + gi * 8;
            Ws[kk0 * 264 + g] = Wp[(size_t)g * K + k0 + kk0];
        }
        // stage X tile (already [k][b], contiguous 4KB)
        ((float4*)Xs)[threadIdx.x] = ((const float4*)(Ap + (size_t)k0 * B))[threadIdx.x];
        __syncthreads();
#pragma unroll
        for (int kk = 0; kk < 32; kk++) {
            float4 w0 = *(const float4*)&Ws[kk * 264 + gT * 8];
            float4 w1 = *(const float4*)&Ws[kk * 264 + gT * 8 + 4];
            float4 xv = ((const float4*)Xs)[kk * 8 + bT];
            float w[8] = {w0.x, w0.y, w0.z, w0.w, w1.x, w1.y, w1.z, w1.w};
            float xr[4] = {xv.x, xv.y, xv.z, xv.w};
#pragma unroll
            for (int gi = 0; gi < 8; gi++)
#pragma unroll
                for (int bi = 0; bi < 4; bi++)
                    acc[gi][bi] += w[gi] * xr[bi];
        }
        __syncthreads();
    }

    int gbase = g0 + gT * 8;
    int bbase = bT * 4;
#pragma unroll
    for (int gi = 0; gi < 8; gi++) {
        float bias = bih[dir * H3 + gbase + gi];
        float4 o = make_float4(acc[gi][0] + bias, acc[gi][1] + bias,
                               acc[gi][2] + bias, acc[gi][3] + bias);
        *(float4*)&g_Xi[(((size_t)dir * T + t) * H3 + gbase + gi) * B + bbase] = o;
    }
}

// ---------------- persistent bidirectional GRU recurrence --------------------
// 128 CTAs: dir = cta/64, hidden slice J0 = (cta%64)*8 (24 gate rows).
// smem: Ws [k][rq]float4 (64KB) + Hs [k][b] (64KB) + partials (12KB) + bias.
#define SMEM_REC ((16384 + 16384 + 3072 + 32) * 4)

__global__ __launch_bounds__(256) void gru_rec(const float* __restrict__ whh,
                                               const float* __restrict__ bhh,
                                               float* __restrict__ y,
                                               float* __restrict__ out,
                                               int layer) {
    extern __shared__ float smem[];
    float* Ws = smem;               // 512*8*4
    float* Hs = smem + 16384;       // 512*32
    float* Ps = smem + 32768;       // 4*24*32
    float* bias_s = smem + 32768 + 3072;

    int cta = blockIdx.x;
    int dir = cta >> 6;
    int J0  = (cta & 63) * HID_PER_CTA;
    int tid = threadIdx.x;

    // load W_hh slice into smem (one time; W_s[k][rq] float4 with gates in xyz)
    const float* wp = whh + (size_t)dir * H3 * H;
    for (int r = 0; r < 24; r++) {
        int rq = r / 3, gi = r - rq * 3;
        int grow = gi * H + J0 + rq;
        for (int k = tid; k < H; k += 256)
            Ws[(k * 8 + rq) * 4 + gi] = wp[(size_t)grow * H + k];
    }
    if (tid < 24) {
        int rq = tid / 3, gi = tid - rq * 3;
        bias_s[tid] = bhh[dir * H3 + gi * H + J0 + rq];
    }
    // zero h buffer 0 (our slice)
    g_h[0][dir * H * B + (J0 + (tid >> 5)) * B + (tid & 31)] = 0.f;
    __threadfence();
    grid_sync();

    int ks = tid >> 6;               // k-split 0..3
    int rq = (tid >> 3) & 7;         // hidden-in-CTA (row triple)
    int bq = tid & 7;                // batch quad
    int j  = tid >> 5;               // epilogue hidden 0..7
    int b  = tid & 31;               // epilogue batch

    const float4* Ws4 = (const float4*)Ws;
    float4* Hs4 = (float4*)Hs;
    float4* Ps4 = (float4*)Ps;

    for (int step = 0; step < T; step++) {
        int t   = dir ? (T - 1 - step) : step;
        int cur = step & 1, nxt = cur ^ 1;

        // prefetch Xi (independent of h)
        const float* xip = g_Xi + (((size_t)dir * T + t) * H3 + J0 + j) * B + b;
        float xi0 = __ldg(xip);
        float xi1 = __ldg(xip + (size_t)H * B);
        float xi2 = __ldg(xip + (size_t)2 * H * B);

        // reload h (L2-coherent; bypass L1)
        const float4* hp = (const float4*)(g_h[cur] + dir * H * B);
#pragma unroll
        for (int i = 0; i < 16; i++)
            Hs4[tid + i * 256] = __ldcg(hp + tid + i * 256);
        __syncthreads();

        // per-step GEMM slice: rows (rq*3..+2) x batches (bq*4..+3), k-split
        float a0x = 0, a0y = 0, a0z = 0, a0w = 0;
        float a1x = 0, a1y = 0, a1z = 0, a1w = 0;
        float a2x = 0, a2y = 0, a2z = 0, a2w = 0;
        int kbeg = ks * 128;
#pragma unroll 4
        for (int k = kbeg; k < kbeg + 128; k++) {
            float4 w4 = Ws4[k * 8 + rq];
            float4 h4 = Hs4[k * 8 + bq];
            a0x += w4.x * h4.x; a0y += w4.x * h4.y; a0z += w4.x * h4.z; a0w += w4.x * h4.w;
            a1x += w4.y * h4.x; a1y += w4.y * h4.y; a1z += w4.y * h4.z; a1w += w4.y * h4.w;
            a2x += w4.z * h4.x; a2y += w4.z * h4.y; a2z += w4.z * h4.z; a2w += w4.z * h4.w;
        }
        Ps4[(ks * 768 + (rq * 3 + 0) * 32) / 4 + bq] = make_float4(a0x, a0y, a0z, a0w);
        Ps4[(ks * 768 + (rq * 3 + 1) * 32) / 4 + bq] = make_float4(a1x, a1y, a1z, a1w);
        Ps4[(ks * 768 + (rq * 3 + 2) * 32) / 4 + bq] = make_float4(a2x, a2y, a2z, a2w);
        __syncthreads();

        // epilogue: thread (j, b)
        float s0 = 0.f, s1 = 0.f, s2 = 0.f;
#pragma unroll
        for (int q = 0; q < 4; q++) {
            s0 += Ps[q * 768 + (j * 3 + 0) * 32 + b];
            s1 += Ps[q * 768 + (j * 3 + 1) * 32 + b];
            s2 += Ps[q * 768 + (j * 3 + 2) * 32 + b];
        }
        float hr = s0 + bias_s[j * 3 + 0];
        float hz = s1 + bias_s[j * 3 + 1];
        float hn = s2 + bias_s[j * 3 + 2];
        float hold = Hs[(J0 + j) * 32 + b];
        float r = 1.f / (1.f + __expf(-(xi0 + hr)));
        float z = 1.f / (1.f + __expf(-(xi1 + hz)));
        float n = tanhf(xi2 + r * hn);
        float hnew = (1.f - z) * n + z * hold;

        g_h[nxt][dir * H * B + (J0 + j) * B + b] = hnew;
        y[((size_t)t * FEAT + dir * H + (J0 + j)) * B + b] = hnew;
        if (step == T - 1)
            out[(2 * layer + dir) * (B * H) + b * H + (J0 + j)] = hnew;

        grid_sync();
    }
}

// ---------------- host launcher ---------------------------------------------
extern "C" void kernel_launch(void* const* d_in, const int* in_sizes, int n_in,
                              void* d_out, int out_size) {
    const float* x        = (const float*)d_in[0];
    const float* w_ih_l0  = (const float*)d_in[1];
    const float* w_hh_l0  = (const float*)d_in[2];
    const float* b_ih_l0  = (const float*)d_in[3];
    const float* b_hh_l0  = (const float*)d_in[4];
    const float* w_ih_lr  = (const float*)d_in[5];
    const float* w_hh_lr  = (const float*)d_in[6];
    const float* b_ih_lr  = (const float*)d_in[7];
    const float* b_hh_lr  = (const float*)d_in[8];
    float* out = (float*)d_out;

    cudaFuncSetAttribute(gru_rec, cudaFuncAttributeMaxDynamicSharedMemorySize, SMEM_REC);

    void *pxT, *pyA, *pyB;
    cudaGetSymbolAddress(&pxT, g_xT);
    cudaGetSymbolAddress(&pyA, g_yA);
    cudaGetSymbolAddress(&pyB, g_yB);
    float* xT = (float*)pxT;
    float* yA = (float*)pyA;
    float* yB = (float*)pyB;

    dim3 ggrid(T, 12);

    // layer 0
    transpose_x<<<T, 256>>>(x);
    gemm_xi<<<ggrid, 256>>>(xT, w_ih_l0, b_ih_l0, INPUT_DIM);
    gru_rec<<<NCTAS_REC, 256, SMEM_REC>>>(w_hh_l0, b_hh_l0, yA, out, 0);

    // layer 1
    gemm_xi<<<ggrid, 256>>>(yA, w_ih_lr, b_ih_lr, FEAT);
    gru_rec<<<NCTAS_REC, 256, SMEM_REC>>>(w_hh_lr, b_hh_lr, yB, out, 1);

    // layer 2
    gemm_xi<<<ggrid, 256>>>(yB, w_ih_lr + (size_t)2 * H3 * FEAT,
                            b_ih_lr + 2 * H3, FEAT);
    gru_rec<<<NCTAS_REC, 256, SMEM_REC>>>(w_hh_lr + (size_t)2 * H3 * H,
                                          b_hh_lr + 2 * H3, yA, out, 2);
}

// round 3
// speedup vs baseline: 2.6736x; 2.6736x over previous
#include <cuda_runtime.h>
#include <math.h>

#define T 1024
#define B 32
#define INPUT_DIM 256
#define H 512
#define H3 1536
#define FEAT (2*H)

#define NCTAS_REC 128

// ---- device scratch ----
__device__ __align__(256) float g_xT[T * INPUT_DIM * B];              // tf32 bits
__device__ __align__(256) float g_Xi[2u * T * H3 * B];                // fp32
__device__ __align__(256) float g_yA[T * FEAT * B];                   // tf32 bits
__device__ __align__(256) float g_yB[T * FEAT * B];                   // tf32 bits
__device__ __align__(256) float g_h[2][2][H][B];                      // fp32 state
__device__ unsigned long long g_cnt;
__device__ unsigned long long g_rel;

// ---------------- helpers ----------------------------------------------------
__device__ __forceinline__ unsigned cvt_tf32(float f) {
    unsigned r;
    asm("cvt.rna.tf32.f32 %0, %1;" : "=r"(r) : "f"(f));
    return r;
}

__device__ __forceinline__ void mma8(float* d, const unsigned* a,
                                     unsigned b0, unsigned b1) {
    asm("mma.sync.aligned.m16n8k8.row.col.f32.tf32.tf32.f32 "
        "{%0,%1,%2,%3},{%4,%5,%6,%7},{%8,%9},{%0,%1,%2,%3};"
        : "+f"(d[0]), "+f"(d[1]), "+f"(d[2]), "+f"(d[3])
        : "r"(a[0]), "r"(a[1]), "r"(a[2]), "r"(a[3]), "r"(b0), "r"(b1));
}

// ---------------- grid barrier (monotonic ticket; replay-safe) ---------------
__device__ __forceinline__ void grid_sync() {
    __syncthreads();
    if (threadIdx.x == 0) {
        __threadfence();
        unsigned long long a = atomicAdd(&g_cnt, 1ull) + 1ull;
        unsigned long long goal = ((a + NCTAS_REC - 1) / NCTAS_REC) * NCTAS_REC;
        if (a == goal) {
            atomicMax(&g_rel, goal);
        } else {
            while (*((volatile unsigned long long*)&g_rel) < goal) { }
        }
        __threadfence();
    }
    __syncthreads();
}

// ---------------- transpose + tf32 round: x[t][b][k] -> g_xT[t][k][b] --------
__global__ void transpose_x(const float* __restrict__ x) {
    __shared__ float sm[B][INPUT_DIM + 1];
    int t = blockIdx.x;
    const float* xin = x + (size_t)t * B * INPUT_DIM;
    for (int i = threadIdx.x; i < B * INPUT_DIM; i += 256) {
        int b = i >> 8, k = i & 255;
        sm[b][k] = xin[i];
    }
    __syncthreads();
    float* xo = g_xT + (size_t)t * INPUT_DIM * B;
    for (int i = threadIdx.x; i < B * INPUT_DIM; i += 256) {
        int k = i >> 5, b = i & 31;
        xo[i] = __uint_as_float(cvt_tf32(sm[b][k]));
    }
}

// ---------------- Xi GEMM (tf32 tensor cores) --------------------------------
// Xi[dir][t][g][b] = sum_k W[dir][g][k] * A[t][k][b] + bih[dir][g]
// A holds tf32 bits. CTA tile: 128 g x (4 t * 32 b). 8 warps: 4 m x 2 n.
__global__ __launch_bounds__(256) void gemm_xi(const float* __restrict__ A,
                                               const float* __restrict__ Wih,
                                               const float* __restrict__ bih,
                                               int K) {
    __shared__ float Ws[128 * 36];       // [g][kk] stride 36 (tf32 bits)
    __shared__ float xs[4 * 32 * 40];    // [t'][kk][b] stride 40 (tf32 bits)

    int t0  = blockIdx.x * 4;
    int dir = blockIdx.y / 12;
    int g0  = (blockIdx.y % 12) * 128;
    int tid = threadIdx.x;
    int l   = tid & 31;
    int w   = tid >> 5;
    int wm  = w & 3;          // m-warp: rows g0 + wm*32 .. +31
    int wn  = w >> 2;         // n-warp: cols wn*64 .. +63

    const float* Wp = Wih + ((size_t)dir * H3 + g0) * (size_t)K;

    float acc[2][8][4];
#pragma unroll
    for (int mt = 0; mt < 2; mt++)
#pragma unroll
        for (int q = 0; q < 8; q++)
#pragma unroll
            for (int s = 0; s < 4; s++) acc[mt][q][s] = 0.f;

    for (int k0 = 0; k0 < K; k0 += 32) {
        // stage W (cvt to tf32)
#pragma unroll
        for (int i = 0; i < 4; i++) {
            int fid = tid + i * 256;
            int g = fid >> 3, kq = fid & 7;
            float4 wv = *(const float4*)&Wp[(size_t)g * K + k0 + kq * 4];
            float4 o;
            o.x = __uint_as_float(cvt_tf32(wv.x));
            o.y = __uint_as_float(cvt_tf32(wv.y));
            o.z = __uint_as_float(cvt_tf32(wv.z));
            o.w = __uint_as_float(cvt_tf32(wv.w));
            *(float4*)&Ws[g * 36 + kq * 4] = o;
        }
        // stage x (already tf32)
#pragma unroll
        for (int i = 0; i < 4; i++) {
            int fid = tid + i * 256;
            int tp = fid >> 8, k = (fid >> 3) & 31, bq = fid & 7;
            float4 xv = *(const float4*)&A[((size_t)(t0 + tp) * K + k0 + k) * B + bq * 4];
            *(float4*)&xs[tp * 1280 + k * 40 + bq * 4] = xv;
        }
        __syncthreads();

#pragma unroll
        for (int ki = 0; ki < 4; ki++) {
            unsigned a[2][4];
#pragma unroll
            for (int mt = 0; mt < 2; mt++) {
                int row = wm * 32 + mt * 16 + (l >> 2);
                int kk = ki * 8 + (l & 3);
                a[mt][0] = __float_as_uint(Ws[row * 36 + kk]);
                a[mt][1] = __float_as_uint(Ws[(row + 8) * 36 + kk]);
                a[mt][2] = __float_as_uint(Ws[row * 36 + kk + 4]);
                a[mt][3] = __float_as_uint(Ws[(row + 8) * 36 + kk + 4]);
            }
#pragma unroll
            for (int q = 0; q < 8; q++) {
                int n = wn * 64 + q * 8;
                int tp = n >> 5, bb = (n & 31) + (l >> 2);
                int kk = ki * 8 + (l & 3);
                unsigned b0 = __float_as_uint(xs[tp * 1280 + kk * 40 + bb]);
                unsigned b1 = __float_as_uint(xs[tp * 1280 + (kk + 4) * 40 + bb]);
                mma8(acc[0][q], a[0], b0, b1);
                mma8(acc[1][q], a[1], b0, b1);
            }
        }
        __syncthreads();
    }

    // epilogue: bias + store fp32
    float bias[2][2];
#pragma unroll
    for (int mt = 0; mt < 2; mt++) {
        int r = g0 + wm * 32 + mt * 16 + (l >> 2);
        bias[mt][0] = bih[dir * H3 + r];
        bias[mt][1] = bih[dir * H3 + r + 8];
    }
#pragma unroll
    for (int mt = 0; mt < 2; mt++)
#pragma unroll
        for (int q = 0; q < 8; q++) {
            int n = wn * 64 + q * 8;
            int tp = n >> 5;
            int bb = (n & 31) + (l & 3) * 2;
            int r = g0 + wm * 32 + mt * 16 + (l >> 2);
            size_t base = (size_t)(dir * T + t0 + tp) * H3;
            float2 v0 = make_float2(acc[mt][q][0] + bias[mt][0],
                                    acc[mt][q][1] + bias[mt][0]);
            float2 v1 = make_float2(acc[mt][q][2] + bias[mt][1],
                                    acc[mt][q][3] + bias[mt][1]);
            *(float2*)&g_Xi[(base + r) * B + bb] = v0;
            *(float2*)&g_Xi[(base + r + 8) * B + bb] = v1;
        }
}

// ---------------- persistent recurrence (tf32 mma, W in registers) -----------
// 128 CTAs: dir = cta>>6, J0 = (cta&63)*8 -> 24 gate rows (gate*8 + j).
// Warp ws owns k-slice [ws*64, ws*64+64). A-frags preloaded once.
#define HS_F (512 * 40)
#define PS_F (8 * 24 * 32)
#define SMEM_REC (120 * 1024)

__global__ __launch_bounds__(256) void gru_rec(const float* __restrict__ whh,
                                               const float* __restrict__ bhh,
                                               float* __restrict__ y,
                                               float* __restrict__ out,
                                               int layer) {
    extern __shared__ float smem[];
    float* Hs = smem;                    // [k][b] stride 40
    float* Ps = smem + HS_F;             // [ws][24][32]
    float* bias_s = smem + HS_F + PS_F;

    int cta = blockIdx.x;
    int dir = cta >> 6;
    int J0  = (cta & 63) * 8;
    int tid = threadIdx.x;
    int l   = tid & 31;
    int ws  = tid >> 5;
    int j   = tid >> 5;      // epilogue hidden 0..7
    int b   = tid & 31;      // epilogue batch

    // preload A fragments (W_hh) into registers, tf32
    unsigned afr[2][8][4];
#pragma unroll
    for (int mt = 0; mt < 2; mt++)
#pragma unroll
        for (int ki = 0; ki < 8; ki++)
#pragma unroll
            for (int s = 0; s < 4; s++) {
                int r = mt * 16 + (l >> 2) + (s & 1) * 8;
                int k = ws * 64 + ki * 8 + (l & 3) + (s >> 1) * 4;
                float wv = 0.f;
                if (r < 24)
                    wv = whh[(size_t)dir * H3 * H +
                             (size_t)((r >> 3) * H + J0 + (r & 7)) * H + k];
                afr[mt][ki][s] = cvt_tf32(wv);
            }
    if (tid < 24)
        bias_s[tid] = bhh[dir * H3 + (tid >> 3) * H + J0 + (tid & 7)];

    // zero initial h (buffer 0, our slice)
    g_h[0][dir][J0 + j][b] = 0.f;
    __threadfence();
    grid_sync();

    for (int step = 0; step < T; step++) {
        int t   = dir ? (T - 1 - step) : step;
        int cur = step & 1, nxt = cur ^ 1;

        // Xi prefetch (independent of h)
        const float* xip = g_Xi + (((size_t)dir * T + t) * H3 + J0 + j) * B + b;
        float xi0 = __ldg(xip);
        float xi1 = __ldg(xip + (size_t)H * B);
        float xi2 = __ldg(xip + (size_t)2 * H * B);

        // stage h (L2-coherent)
        const float4* hp = (const float4*)&g_h[cur][dir][0][0];
#pragma unroll
        for (int i = 0; i < 16; i++) {
            int idx = tid + i * 256;
            int k = idx >> 3, bq = idx & 7;
            float4 v = __ldcg(hp + idx);
            *(float4*)&Hs[k * 40 + bq * 4] = v;
        }
        __syncthreads();

        // mma: 24 (pad 32) x 32 x 64 per warp
        float acc[2][4][4];
#pragma unroll
        for (int mt = 0; mt < 2; mt++)
#pragma unroll
            for (int q = 0; q < 4; q++)
#pragma unroll
                for (int s = 0; s < 4; s++) acc[mt][q][s] = 0.f;

#pragma unroll
        for (int ki = 0; ki < 8; ki++) {
            int kk = ws * 64 + ki * 8 + (l & 3);
#pragma unroll
            for (int q = 0; q < 4; q++) {
                int bb = q * 8 + (l >> 2);
                unsigned b0 = cvt_tf32(Hs[kk * 40 + bb]);
                unsigned b1 = cvt_tf32(Hs[(kk + 4) * 40 + bb]);
                mma8(acc[0][q], afr[0][ki], b0, b1);
                mma8(acc[1][q], afr[1][ki], b0, b1);
            }
        }

        // partials to smem (rows 24..31 dropped)
#pragma unroll
        for (int q = 0; q < 4; q++) {
            int col = q * 8 + (l & 3) * 2;
            int r0 = (l >> 2);
            *(float2*)&Ps[ws * 768 + r0 * 32 + col] =
                make_float2(acc[0][q][0], acc[0][q][1]);
            *(float2*)&Ps[ws * 768 + (r0 + 8) * 32 + col] =
                make_float2(acc[0][q][2], acc[0][q][3]);
            *(float2*)&Ps[ws * 768 + (r0 + 16) * 32 + col] =
                make_float2(acc[1][q][0], acc[1][q][1]);
        }
        __syncthreads();

        // reduce 8-way + gates (thread j,b)
        float s0 = 0.f, s1 = 0.f, s2 = 0.f;
#pragma unroll
        for (int wq = 0; wq < 8; wq++) {
            s0 += Ps[wq * 768 + j * 32 + b];
            s1 += Ps[wq * 768 + (8 + j) * 32 + b];
            s2 += Ps[wq * 768 + (16 + j) * 32 + b];
        }
        float hold = Hs[(J0 + j) * 40 + b];
        float r = 1.f / (1.f + __expf(-(xi0 + s0 + bias_s[j])));
        float z = 1.f / (1.f + __expf(-(xi1 + s1 + bias_s[8 + j])));
        float n = tanhf(xi2 + r * (s2 + bias_s[16 + j]));
        float hnew = (1.f - z) * n + z * hold;

        g_h[nxt][dir][J0 + j][b] = hnew;
        y[((size_t)t * FEAT + dir * H + (J0 + j)) * B + b] =
            __uint_as_float(cvt_tf32(hnew));
        if (step == T - 1)
            out[(2 * layer + dir) * (B * H) + b * H + (J0 + j)] = hnew;

        grid_sync();
    }
}

// ---------------- host launcher ---------------------------------------------
extern "C" void kernel_launch(void* const* d_in, const int* in_sizes, int n_in,
                              void* d_out, int out_size) {
    const float* x        = (const float*)d_in[0];
    const float* w_ih_l0  = (const float*)d_in[1];
    const float* w_hh_l0  = (const float*)d_in[2];
    const float* b_ih_l0  = (const float*)d_in[3];
    const float* b_hh_l0  = (const float*)d_in[4];
    const float* w_ih_lr  = (const float*)d_in[5];
    const float* w_hh_lr  = (const float*)d_in[6];
    const float* b_ih_lr  = (const float*)d_in[7];
    const float* b_hh_lr  = (const float*)d_in[8];
    float* out = (float*)d_out;

    cudaFuncSetAttribute(gru_rec, cudaFuncAttributeMaxDynamicSharedMemorySize,
                         SMEM_REC);

    void *pxT, *pyA, *pyB;
    cudaGetSymbolAddress(&pxT, g_xT);
    cudaGetSymbolAddress(&pyA, g_yA);
    cudaGetSymbolAddress(&pyB, g_yB);
    float* xT = (float*)pxT;
    float* yA = (float*)pyA;
    float* yB = (float*)pyB;

    dim3 ggrid(T / 4, 24);

    // layer 0
    transpose_x<<<T, 256>>>(x);
    gemm_xi<<<ggrid, 256>>>(xT, w_ih_l0, b_ih_l0, INPUT_DIM);
    gru_rec<<<NCTAS_REC, 256, SMEM_REC>>>(w_hh_l0, b_hh_l0, yA, out, 0);

    // layer 1
    gemm_xi<<<ggrid, 256>>>(yA, w_ih_lr, b_ih_lr, FEAT);
    gru_rec<<<NCTAS_REC, 256, SMEM_REC>>>(w_hh_lr, b_hh_lr, yB, out, 1);

    // layer 2
    gemm_xi<<<ggrid, 256>>>(yB, w_ih_lr + (size_t)2 * H3 * FEAT,
                            b_ih_lr + 2 * H3, FEAT);
    gru_rec<<<NCTAS_REC, 256, SMEM_REC>>>(w_hh_lr + (size_t)2 * H3 * H,
                                          b_hh_lr + 2 * H3, yA, out, 2);
}